// round 8
// baseline (speedup 1.0000x reference)
#include <cuda_runtime.h>
#include <cuda_bf16.h>
#include <cstdint>

// EMA filter: out[d,l] = sum_n p[d,n] * q[d,n]^l * gamma[d,n]
// D=2048, N=16, L=4096, q in [0.05, 0.95].
// R8 = R7 (heterogeneous compute/fill grid, fixed active range 1024,
// k=2 fold, packed f32x2) + MUFU elimination:
// MUFU accounting showed R7 was exp2f-throughput-bound (~2112 MUFU/block
// = ~8 us chip-wide, matching measured time). Replace per-thread
// 16x exp2f power init with block-shared factored tables
//   q^t = q^(16a) * q^b,  a = t>>4, b = t&15
// built with 192 exp2f total (9x MUFU cut); per-thread init becomes
// 16 conflict-free LDS.64 + 8 mul2 on the idle FMA pipe.

#define D_DIM 2048
#define N_DIM 16
#define L_DIM 4096
#define TPB   128
#define NP    (N_DIM / 2)   // 8 packed n-pairs
#define HACT  512           // fold offset (active length 1024)
#define ITERS 4             // HACT / TPB

__device__ __forceinline__ unsigned long long pack2(float lo, float hi) {
    unsigned long long r;
    asm("mov.b64 %0, {%1, %2};" : "=l"(r) : "f"(lo), "f"(hi));
    return r;
}
__device__ __forceinline__ void unpack2(unsigned long long v, float& lo, float& hi) {
    asm("mov.b64 {%0, %1}, %2;" : "=f"(lo), "=f"(hi) : "l"(v));
}
__device__ __forceinline__ unsigned long long fma2(unsigned long long a,
                                                   unsigned long long b,
                                                   unsigned long long c) {
    unsigned long long r;
    asm("fma.rn.f32x2 %0, %1, %2, %3;" : "=l"(r) : "l"(a), "l"(b), "l"(c));
    return r;
}
__device__ __forceinline__ unsigned long long mul2(unsigned long long a,
                                                   unsigned long long b) {
    unsigned long long r;
    asm("mul.rn.f32x2 %0, %1, %2;" : "=l"(r) : "l"(a), "l"(b));
    return r;
}
__device__ __forceinline__ unsigned long long add2(unsigned long long a,
                                                   unsigned long long b) {
    unsigned long long r;
    asm("add.rn.f32x2 %0, %1, %2;" : "=l"(r) : "l"(a), "l"(b));
    return r;
}

__global__ __launch_bounds__(TPB, 6)
void ema_filter_kernel(const float* __restrict__ p,
                       const float* __restrict__ q,
                       const float* __restrict__ gamma,
                       float* __restrict__ out) {
    const int bid  = blockIdx.x;
    const int grp  = bid / 3;
    const int role = bid - 3 * grp;     // 0,1 compute; 2 fill
    const int tid  = threadIdx.x;

    if (role == 2) {
        // FILL: zero columns [1024, 4096) for d = 2*grp and 2*grp+1.
        float4 z = make_float4(0.0f, 0.0f, 0.0f, 0.0f);
        float4* o4 = (float4*)(out + (size_t)(2 * grp) * L_DIM);
#pragma unroll
        for (int j = 0; j < 6; j++) {
            o4[256 + j * TPB + tid]  = z;
            o4[1280 + j * TPB + tid] = z;
        }
        return;
    }

    // COMPUTE for d:
    const int d = 2 * grp + role;

    __shared__ float s_c[N_DIM];    // p * gamma
    __shared__ float s_ck[N_DIM];   // p * gamma * q^512
    __shared__ float s_lq[N_DIM];   // log2(q)
    __shared__ float s_m[N_DIM];    // q^128
    __shared__ float2 s_A[8][9];    // [a][j] = (q_{2j}^(16a), q_{2j+1}^(16a))
    __shared__ float2 s_B[16][9];   // [b][j] = (q_{2j}^b,     q_{2j+1}^b)

    if (tid < N_DIM) {
        const int idx = d * N_DIM + tid;
        float qv = q[idx];
        float lq = __log2f(qv);
        float c  = p[idx] * gamma[idx];
        s_lq[tid] = lq;
        s_c[tid]  = c;
        s_m[tid]  = exp2f(128.0f * lq);
        s_ck[tid] = c * exp2f((float)HACT * lq);  // underflow->0 ok
    }
    __syncthreads();

    // Build factored power tables: 192 exp2f total for the block.
    {
        const int j = tid & 7;
        if (tid < 64) {                   // A: a = tid>>3 in 0..7
            const int a = tid >> 3;
            const float e = 16.0f * (float)a;
            s_A[a][j] = make_float2(exp2f(e * s_lq[2 * j]),
                                    exp2f(e * s_lq[2 * j + 1]));
        }
        const int b = tid >> 3;           // 0..15
        const float fb = (float)b;
        s_B[b][j] = make_float2(exp2f(fb * s_lq[2 * j]),
                                exp2f(fb * s_lq[2 * j + 1]));
    }
    __syncthreads();

    // Per-thread packed state: w = q^tid = q^(16a) * q^b from tables.
    unsigned long long c2[NP], ck2[NP], m2[NP], w2[NP];
    const int ia = tid >> 4;
    const int ib = tid & 15;
#pragma unroll
    for (int j = 0; j < NP; j++) {
        float2 av = s_A[ia][j];
        float2 bv = s_B[ib][j];
        w2[j]  = mul2(pack2(av.x, av.y), pack2(bv.x, bv.y));
        c2[j]  = pack2(s_c[2 * j],  s_c[2 * j + 1]);
        ck2[j] = pack2(s_ck[2 * j], s_ck[2 * j + 1]);
        m2[j]  = pack2(s_m[2 * j],  s_m[2 * j + 1]);
    }

    float* o = out + (size_t)d * L_DIM + tid;

#pragma unroll
    for (int i = 0; i < ITERS; i++) {
        unsigned long long a0 = 0ull, a1 = 0ull, b0 = 0ull, b1 = 0ull;
#pragma unroll
        for (int j = 0; j < NP; j += 2) {
            a0 = fma2(c2[j],      w2[j],     a0);
            a1 = fma2(c2[j + 1],  w2[j + 1], a1);
            b0 = fma2(ck2[j],     w2[j],     b0);
            b1 = fma2(ck2[j + 1], w2[j + 1], b1);
        }
        a0 = add2(a0, a1);
        b0 = add2(b0, b1);
        float alo, ahi, blo, bhi;
        unpack2(a0, alo, ahi);
        unpack2(b0, blo, bhi);
        o[i * TPB]        = alo + ahi;
        o[i * TPB + HACT] = blo + bhi;
        if (i < ITERS - 1) {
#pragma unroll
            for (int j = 0; j < NP; j++) w2[j] = mul2(w2[j], m2[j]);
        }
    }
}

extern "C" void kernel_launch(void* const* d_in, const int* in_sizes, int n_in,
                              void* d_out, int out_size) {
    const float* p     = (const float*)d_in[0];
    const float* q     = (const float*)d_in[1];
    const float* gamma = (const float*)d_in[2];
    float* out = (float*)d_out;
    ema_filter_kernel<<<3 * (D_DIM / 2), TPB>>>(p, q, gamma, out);
}